// round 15
// baseline (speedup 1.0000x reference)
#include <cuda_runtime.h>
#include <cstdint>

// Inputs (metadata order):
// 0 mu_new (B*N) 1 sigma_new 2 mu_old 3 sigma_old 4 action  -- all (B,N) f32
// 5 value_new (B) 6 value_old 7 adv 8 return_ 9 weight      -- all (B,) f32
// Output: 5 f32 scalars: policy_loss, value_loss, entropy_loss, approx_kl, clipfrac
//
// Bulk-async (UBLKCP) double-buffered pipeline:
//  - 148 CTAs x 512 threads, 64 rows/chunk, 2 SMEM buffers of 83.2KB
//  - one thread issues cp.async.bulk for chunk k+2 while 16 warps compute chunk k
//  - compute identical math to the proven LDG kernel (half-warp per row)

#define HLP 0.9189385332046727f   // 0.5*log(2*pi)

#define ROWS_PER_CHUNK 64
#define VEC_BYTES   (ROWS_PER_CHUNK * 256)                  // 16384 per (B,64) array
#define SCL_BYTES   (ROWS_PER_CHUNK * 4)                    // 256 per (B,) array
#define BUF_BYTES   (5 * VEC_BYTES + 5 * SCL_BYTES)         // 83200
#define SMEM_MBAR   (2 * BUF_BYTES)                         // 166400
#define SMEM_TOTAL  (SMEM_MBAR + 64)

// offsets within one buffer
#define OFF_MN  0
#define OFF_SN  (1 * VEC_BYTES)
#define OFF_MO  (2 * VEC_BYTES)
#define OFF_SO  (3 * VEC_BYTES)
#define OFF_AC  (4 * VEC_BYTES)
#define OFF_SCL (5 * VEC_BYTES)
#define OFF_ADV (OFF_SCL + 0 * SCL_BYTES)
#define OFF_W   (OFF_SCL + 1 * SCL_BYTES)
#define OFF_VN  (OFF_SCL + 2 * SCL_BYTES)
#define OFF_VO  (OFF_SCL + 3 * SCL_BYTES)
#define OFF_RET (OFF_SCL + 4 * SCL_BYTES)

__device__ double g_acc[5];            // zero-init at module load; last CTA re-zeroes
__device__ unsigned int g_done = 0u;   // CTA arrival counter

__device__ __forceinline__ uint32_t smem_u32(const void* p) {
    uint32_t a;
    asm("{ .reg .u64 t; cvta.to.shared.u64 t, %1; cvt.u32.u64 %0, t; }" : "=r"(a) : "l"(p));
    return a;
}

__device__ __forceinline__ void mbar_init(uint32_t mbar, uint32_t count) {
    asm volatile("mbarrier.init.shared.b64 [%0], %1;" :: "r"(mbar), "r"(count) : "memory");
}

__device__ __forceinline__ void mbar_expect_tx(uint32_t mbar, uint32_t bytes) {
    asm volatile("mbarrier.arrive.expect_tx.shared.b64 _, [%0], %1;"
                 :: "r"(mbar), "r"(bytes) : "memory");
}

__device__ __forceinline__ void mbar_wait(uint32_t mbar, uint32_t parity) {
    asm volatile(
        "{\n\t"
        ".reg .pred P;\n\t"
        "WAIT_%=:\n\t"
        "mbarrier.try_wait.parity.acquire.cta.shared::cta.b64 P, [%0], %1, 0x989680;\n\t"
        "@P bra DONE_%=;\n\t"
        "bra WAIT_%=;\n\t"
        "DONE_%=:\n\t"
        "}"
        :: "r"(mbar), "r"(parity) : "memory");
}

__device__ __forceinline__ void bulk_g2s(uint32_t smem_dst, const void* gsrc,
                                         uint32_t bytes, uint32_t mbar) {
    asm volatile(
        "cp.async.bulk.shared::cta.global.mbarrier::complete_tx::bytes [%0], [%1], %2, [%3];"
        :: "r"(smem_dst), "l"(gsrc), "r"(bytes), "r"(mbar) : "memory");
}

__global__ void __launch_bounds__(512, 1) ppo_bulk(
    const float* __restrict__ mu_new, const float* __restrict__ sigma_new,
    const float* __restrict__ mu_old, const float* __restrict__ sigma_old,
    const float* __restrict__ action,
    const float* __restrict__ value_new, const float* __restrict__ value_old,
    const float* __restrict__ adv, const float* __restrict__ return_,
    const float* __restrict__ weight, float* __restrict__ out, int B)
{
    extern __shared__ char smem[];
    const uint32_t smem_base = smem_u32(smem);

    const int tid  = threadIdx.x;
    const int wid  = tid >> 5;                 // 0..15
    const int lane = tid & 31;
    const int half = lane >> 4;
    const int l16  = lane & 15;
    const bool leader = (l16 == 0);

    const int nChunks = B >> 6;                // 4096 chunks of 64 rows
    const int bid   = blockIdx.x;
    const int gstep = gridDim.x;
    const int myCount = (nChunks - bid + gstep - 1) / gstep;

    // mbarriers (one per buffer)
    if (tid == 0) {
        mbar_init(smem_base + SMEM_MBAR + 0, 1);
        mbar_init(smem_base + SMEM_MBAR + 8, 1);
    }
    __syncthreads();

    // issue helper (tid 0 only, inlined)
    auto issue = [&](int k, int buf) {
        const int c = bid + k * gstep;
        const uint32_t mb = smem_base + SMEM_MBAR + buf * 8;
        const uint32_t d  = smem_base + buf * BUF_BYTES;
        const size_t vOff = (size_t)c * VEC_BYTES;
        const size_t sOff = (size_t)c * SCL_BYTES;
        mbar_expect_tx(mb, BUF_BYTES);
        bulk_g2s(d + OFF_MN,  (const char*)mu_new    + vOff, VEC_BYTES, mb);
        bulk_g2s(d + OFF_SN,  (const char*)sigma_new + vOff, VEC_BYTES, mb);
        bulk_g2s(d + OFF_MO,  (const char*)mu_old    + vOff, VEC_BYTES, mb);
        bulk_g2s(d + OFF_SO,  (const char*)sigma_old + vOff, VEC_BYTES, mb);
        bulk_g2s(d + OFF_AC,  (const char*)action    + vOff, VEC_BYTES, mb);
        bulk_g2s(d + OFF_ADV, (const char*)adv       + sOff, SCL_BYTES, mb);
        bulk_g2s(d + OFF_W,   (const char*)weight    + sOff, SCL_BYTES, mb);
        bulk_g2s(d + OFF_VN,  (const char*)value_new + sOff, SCL_BYTES, mb);
        bulk_g2s(d + OFF_VO,  (const char*)value_old + sOff, SCL_BYTES, mb);
        bulk_g2s(d + OFF_RET, (const char*)return_   + sOff, SCL_BYTES, mb);
    };

    // prologue: fill both buffers
    if (tid == 0) {
        if (0 < myCount) issue(0, 0);
        if (1 < myCount) issue(1, 1);
    }

    float a0 = 0.f, a1 = 0.f, a2 = 0.f, a3 = 0.f, a4 = 0.f;
    int phase[2] = {0, 0};

    for (int k = 0; k < myCount; k++) {
        const int buf = k & 1;
        mbar_wait(smem_base + SMEM_MBAR + buf * 8, phase[buf]);
        phase[buf] ^= 1;

        const char* bb = smem + buf * BUF_BYTES;

        // 16 warps x 2 pairs: warp handles pairs (wid) and (wid+16); row = 2*pair+half
        #pragma unroll
        for (int pp = 0; pp < 2; pp++) {
            const int pl = wid + pp * 16;      // pair 0..31
            const int r  = 2 * pl + half;      // local row 0..63
            const int rb = r * 256 + l16 * 16;

            const float4 mn = *(const float4*)(bb + OFF_MN + rb);
            const float4 sn = *(const float4*)(bb + OFF_SN + rb);
            const float4 mo = *(const float4*)(bb + OFF_MO + rb);
            const float4 so = *(const float4*)(bb + OFF_SO + rb);
            const float4 ac = *(const float4*)(bb + OFF_AC + rb);

            float d, sE;
            {
                const float zn0 = __fdividef(ac.x - mn.x, sn.x);
                const float zn1 = __fdividef(ac.y - mn.y, sn.y);
                const float zn2 = __fdividef(ac.z - mn.z, sn.z);
                const float zn3 = __fdividef(ac.w - mn.w, sn.w);
                const float zo0 = __fdividef(ac.x - mo.x, so.x);
                const float zo1 = __fdividef(ac.y - mo.y, so.y);
                const float zo2 = __fdividef(ac.z - mo.z, so.z);
                const float zo3 = __fdividef(ac.w - mo.w, so.w);

                // sum of logs == log of product (sigma in [0.5,1.5])
                sE = __logf((sn.x * sn.y) * (sn.z * sn.w));
                const float lO = __logf((so.x * so.y) * (so.z * so.w));

                d = 0.5f * (((zo0 * zo0 - zn0 * zn0) + (zo1 * zo1 - zn1 * zn1))
                          + ((zo2 * zo2 - zn2 * zn2) + (zo3 * zo3 - zn3 * zn3)))
                  + (lO - sE);
            }

            // width-16 butterfly on d
            #pragma unroll
            for (int off = 8; off; off >>= 1)
                d += __shfl_xor_sync(0xffffffffu, d, off);

            // weight from SMEM (broadcast within half-warp, no SHFL)
            const float wv = *(const float*)(bb + OFF_W + r * 4);
            a2 += sE * wv;                     // per-lane entropy contribution

            if (leader) {
                const float diff  = d;         // logp_new - logp_old
                const float ratio = __expf(diff);

                const float s_adv = *(const float*)(bb + OFF_ADV + r * 4);
                const float s_vn  = *(const float*)(bb + OFF_VN  + r * 4);
                const float s_vo  = *(const float*)(bb + OFF_VO  + r * 4);
                const float s_r   = *(const float*)(bb + OFF_RET + r * 4);

                const float surr1 = ratio * s_adv;
                const float rc    = fminf(fmaxf(ratio, 0.8f), 1.2f);
                float clipped = fminf(surr1, rc * s_adv);
                clipped = fmaxf(clipped, 5.0f * s_adv);      // dual clip
                a0 += clipped * wv;

                a2 += (64.0f * (0.5f + HLP)) * wv;           // per-row constant term

                const float vc = s_vo + fminf(fmaxf(s_vn - s_vo, -0.2f), 0.2f);
                const float d1 = s_r - s_vn;
                const float d2 = s_r - vc;
                a1 += fmaxf(d1 * d1, d2 * d2) * wv;

                a3 -= diff;                                  // logp_old - logp_new
                a4 += (fabsf(ratio - 1.0f) > 0.2f) ? 1.0f : 0.0f;
            }
        }

        __syncthreads();                       // all reads of buf done
        if (tid == 0 && k + 2 < myCount) issue(k + 2, buf);
    }

    // full-warp reduce of the 5 accumulators
    #pragma unroll
    for (int off = 16; off; off >>= 1) {
        a0 += __shfl_xor_sync(0xffffffffu, a0, off);
        a1 += __shfl_xor_sync(0xffffffffu, a1, off);
        a2 += __shfl_xor_sync(0xffffffffu, a2, off);
        a3 += __shfl_xor_sync(0xffffffffu, a3, off);
        a4 += __shfl_xor_sync(0xffffffffu, a4, off);
    }

    __shared__ float part[16][5];
    __shared__ bool  amLast;
    if (lane == 0) {
        part[wid][0] = a0; part[wid][1] = a1; part[wid][2] = a2;
        part[wid][3] = a3; part[wid][4] = a4;
    }
    __syncthreads();

    if (tid < 5) {
        float s = 0.f;
        #pragma unroll
        for (int i = 0; i < 16; i++) s += part[i][tid];
        atomicAdd(&g_acc[tid], (double)s);
    }

    // last-CTA finalization (threadfence reduction pattern)
    __threadfence();
    if (tid == 0) {
        const unsigned int ticket = atomicAdd(&g_done, 1u);
        amLast = (ticket == gridDim.x - 1u);
    }
    __syncthreads();

    if (amLast && tid == 0) {
        const double invB = 1.0 / (double)B;
        out[0] = (float)(-g_acc[0] * invB);        // policy_loss
        out[1] = (float)(0.5 * g_acc[1] * invB);   // value_loss
        out[2] = (float)(g_acc[2] * invB);         // entropy_loss
        out[3] = (float)(g_acc[3] * invB);         // approx_kl
        out[4] = (float)(g_acc[4] * invB);         // clipfrac
        g_acc[0] = 0.0; g_acc[1] = 0.0; g_acc[2] = 0.0;
        g_acc[3] = 0.0; g_acc[4] = 0.0;
        g_done = 0u;
    }
}

extern "C" void kernel_launch(void* const* d_in, const int* in_sizes, int n_in,
                              void* d_out, int out_size) {
    const float* mu_new    = (const float*)d_in[0];
    const float* sigma_new = (const float*)d_in[1];
    const float* mu_old    = (const float*)d_in[2];
    const float* sigma_old = (const float*)d_in[3];
    const float* action    = (const float*)d_in[4];
    const float* value_new = (const float*)d_in[5];
    const float* value_old = (const float*)d_in[6];
    const float* adv       = (const float*)d_in[7];
    const float* return_   = (const float*)d_in[8];
    const float* weight    = (const float*)d_in[9];
    const int B = in_sizes[5];   // value_new element count

    cudaFuncSetAttribute(ppo_bulk, cudaFuncAttributeMaxDynamicSharedMemorySize, SMEM_TOTAL);
    ppo_bulk<<<148, 512, SMEM_TOTAL>>>(mu_new, sigma_new, mu_old, sigma_old, action,
                                       value_new, value_old, adv, return_, weight,
                                       (float*)d_out, B);
}

// round 16
// speedup vs baseline: 1.0104x; 1.0104x over previous
#include <cuda_runtime.h>

// Inputs (metadata order):
// 0 mu_new (B*N) 1 sigma_new 2 mu_old 3 sigma_old 4 action  -- all (B,N) f32
// 5 value_new (B) 6 value_old 7 adv 8 return_ 9 weight      -- all (B,) f32
// Output: 5 f32 scalars: policy_loss, value_loss, entropy_loss, approx_kl, clipfrac
//
// FINAL kernel — session-best measured configuration (53.76us best sample,
// ~6.3 TB/s effective = measured path-independent LTS/HBM cap; floor ~53.6us):
//  - single fused kernel, last-CTA finalize (threadfence reduction)
//  - half-warp per row, float4 LDG.128 .cs streaming loads
//  - 1-deep register software pipeline
//    (2-deep, L2-prefetch instrs, and bulk-async/UBLKCP all measured & regressed)
//  - 5-SHFL per-iteration reduction (d butterfly + weight broadcast)
//  - 592 blocks x 256 threads = 4 CTAs/SM (3/5/8 CTAs per SM all regressed)

#define HLP 0.9189385332046727f   // 0.5*log(2*pi)

__device__ double g_acc[5];            // zero-init at module load; last CTA re-zeroes
__device__ unsigned int g_done = 0u;   // CTA arrival counter

__global__ void __launch_bounds__(256, 4) ppo_fused(
    const float* __restrict__ mu_new, const float* __restrict__ sigma_new,
    const float* __restrict__ mu_old, const float* __restrict__ sigma_old,
    const float* __restrict__ action,
    const float* __restrict__ value_new, const float* __restrict__ value_old,
    const float* __restrict__ adv, const float* __restrict__ return_,
    const float* __restrict__ weight, float* __restrict__ out, int B)
{
    const int lane   = threadIdx.x & 31;
    const int wib    = threadIdx.x >> 5;                       // warp in block
    const int gw     = (blockIdx.x * blockDim.x + threadIdx.x) >> 5;
    const int nwarps = (gridDim.x * blockDim.x) >> 5;
    const int half   = lane >> 4;                              // which row of the pair
    const int l16    = lane & 15;
    const bool leader = (l16 == 0);
    const int srcLane = half << 4;                             // 0 or 16: row leader lane
    const int totalPairs = B >> 1;

    float a0 = 0.f, a1 = 0.f, a2 = 0.f, a3 = 0.f, a4 = 0.f;   // per-thread partials

    // ---- stage-1 register prefetch ----
    float4 mn, sn, mo, so, ac;
    int pair = gw;
    if (pair < totalPairs) {
        const size_t base = (size_t)(pair * 2 + half) * 64 + (size_t)l16 * 4;
        mn = __ldcs((const float4*)(mu_new    + base));
        sn = __ldcs((const float4*)(sigma_new + base));
        mo = __ldcs((const float4*)(mu_old    + base));
        so = __ldcs((const float4*)(sigma_old + base));
        ac = __ldcs((const float4*)(action    + base));
    }

    for (; pair < totalPairs; pair += nwarps) {
        const int row = pair * 2 + half;

        // leader scalar loads, issued early (hidden under compute chain)
        float s_adv = 0.f, s_w = 0.f, s_vn = 0.f, s_vo = 0.f, s_r = 0.f;
        if (leader) {
            s_adv = adv[row];
            s_w   = weight[row];
            s_vn  = value_new[row];
            s_vo  = value_old[row];
            s_r   = return_[row];
        }

        // register prefetch for iteration n+1
        float4 pmn, psn, pmo, pso, pac;
        const int npair = pair + nwarps;
        if (npair < totalPairs) {
            const size_t nb = (size_t)(npair * 2 + half) * 64 + (size_t)l16 * 4;
            pmn = __ldcs((const float4*)(mu_new    + nb));
            psn = __ldcs((const float4*)(sigma_new + nb));
            pmo = __ldcs((const float4*)(mu_old    + nb));
            pso = __ldcs((const float4*)(sigma_old + nb));
            pac = __ldcs((const float4*)(action    + nb));
        }

        // per-lane contributions
        float d, sE;
        {
            const float zn0 = __fdividef(ac.x - mn.x, sn.x);
            const float zn1 = __fdividef(ac.y - mn.y, sn.y);
            const float zn2 = __fdividef(ac.z - mn.z, sn.z);
            const float zn3 = __fdividef(ac.w - mn.w, sn.w);
            const float zo0 = __fdividef(ac.x - mo.x, so.x);
            const float zo1 = __fdividef(ac.y - mo.y, so.y);
            const float zo2 = __fdividef(ac.z - mo.z, so.z);
            const float zo3 = __fdividef(ac.w - mo.w, so.w);

            // sum of logs == log of product (sigma in [0.5,1.5] -> prod in [0.06,5.1])
            sE = __logf((sn.x * sn.y) * (sn.z * sn.w));          // per-lane sum log sigma_new
            const float lO = __logf((so.x * so.y) * (so.z * so.w));

            // d = per-lane (logp_new - logp_old) contribution
            d = 0.5f * (((zo0 * zo0 - zn0 * zn0) + (zo1 * zo1 - zn1 * zn1))
                      + ((zo2 * zo2 - zn2 * zn2) + (zo3 * zo3 - zn3 * zn3)))
              + (lO - sE);
        }

        // reduce d only (width-16 butterfly, 4 SHFLs)
        #pragma unroll
        for (int off = 8; off; off >>= 1)
            d += __shfl_xor_sync(0xffffffffu, d, off);

        // broadcast weight from row leader to its 16 lanes (1 SHFL)
        const float w_bc = __shfl_sync(0xffffffffu, s_w, srcLane);

        // entropy: every lane accumulates its own sE contribution, weighted
        a2 += sE * w_bc;

        if (leader) {   // lanes 0 and 16 are row leaders
            const float diff  = d;                // logp_new - logp_old
            const float ratio = __expf(diff);

            const float surr1 = ratio * s_adv;
            const float rc    = fminf(fmaxf(ratio, 0.8f), 1.2f);
            float clipped = fminf(surr1, rc * s_adv);
            clipped = fmaxf(clipped, 5.0f * s_adv);   // dual clip
            a0 += clipped * s_w;

            a2 += (64.0f * (0.5f + HLP)) * s_w;       // per-row constant entropy term

            const float vc = s_vo + fminf(fmaxf(s_vn - s_vo, -0.2f), 0.2f);
            const float d1 = s_r - s_vn;
            const float d2 = s_r - vc;
            a1 += fmaxf(d1 * d1, d2 * d2) * s_w;

            a3 -= diff;                           // logp_old - logp_new
            a4 += (fabsf(ratio - 1.0f) > 0.2f) ? 1.0f : 0.0f;
        }

        mn = pmn; sn = psn; mo = pmo; so = pso; ac = pac;
    }

    // full-warp reduce of the 5 accumulators
    #pragma unroll
    for (int off = 16; off; off >>= 1) {
        a0 += __shfl_xor_sync(0xffffffffu, a0, off);
        a1 += __shfl_xor_sync(0xffffffffu, a1, off);
        a2 += __shfl_xor_sync(0xffffffffu, a2, off);
        a3 += __shfl_xor_sync(0xffffffffu, a3, off);
        a4 += __shfl_xor_sync(0xffffffffu, a4, off);
    }

    __shared__ float part[8][5];
    __shared__ bool  amLast;
    if (lane == 0) {
        part[wib][0] = a0; part[wib][1] = a1; part[wib][2] = a2;
        part[wib][3] = a3; part[wib][4] = a4;
    }
    __syncthreads();

    if (threadIdx.x < 5) {
        float s = 0.f;
        #pragma unroll
        for (int i = 0; i < 8; i++) s += part[i][threadIdx.x];
        atomicAdd(&g_acc[threadIdx.x], (double)s);
    }

    // last-CTA finalization (threadfence reduction pattern)
    __threadfence();
    if (threadIdx.x == 0) {
        const unsigned int ticket = atomicAdd(&g_done, 1u);
        amLast = (ticket == gridDim.x - 1u);
    }
    __syncthreads();

    if (amLast && threadIdx.x == 0) {
        const double invB = 1.0 / (double)B;
        out[0] = (float)(-g_acc[0] * invB);        // policy_loss
        out[1] = (float)(0.5 * g_acc[1] * invB);   // value_loss
        out[2] = (float)(g_acc[2] * invB);         // entropy_loss
        out[3] = (float)(g_acc[3] * invB);         // approx_kl
        out[4] = (float)(g_acc[4] * invB);         // clipfrac
        // reset for the next (graph-replayed) invocation
        g_acc[0] = 0.0; g_acc[1] = 0.0; g_acc[2] = 0.0;
        g_acc[3] = 0.0; g_acc[4] = 0.0;
        g_done = 0u;
    }
}

extern "C" void kernel_launch(void* const* d_in, const int* in_sizes, int n_in,
                              void* d_out, int out_size) {
    const float* mu_new    = (const float*)d_in[0];
    const float* sigma_new = (const float*)d_in[1];
    const float* mu_old    = (const float*)d_in[2];
    const float* sigma_old = (const float*)d_in[3];
    const float* action    = (const float*)d_in[4];
    const float* value_new = (const float*)d_in[5];
    const float* value_old = (const float*)d_in[6];
    const float* adv       = (const float*)d_in[7];
    const float* return_   = (const float*)d_in[8];
    const float* weight    = (const float*)d_in[9];
    const int B = in_sizes[5];   // value_new element count

    const int blocks = 592;      // 4 CTAs/SM on 148 SMs (measured-best configuration)
    ppo_fused<<<blocks, 256>>>(mu_new, sigma_new, mu_old, sigma_old, action,
                               value_new, value_old, adv, return_, weight,
                               (float*)d_out, B);
}